// round 7
// baseline (speedup 1.0000x reference)
#include <cuda_runtime.h>

#define SEQ   600
#define BATCH 4096
#define INP   6
#define HID   30
#define OUTD  61
#define VLEN  36              // x(6) + h(30), no pad
#define NTHR  512             // 16 warps = 8 pairs
#define NPAIR 8
#define BPP   4               // batches per pair
#define BBLK  (NPAIR * BPP)   // 32 batches per block
#define NBLK  (BATCH / BBLK)  // 128 blocks

typedef unsigned long long ull;

// ---------------- preprocessed weights (device globals) ----------------
__device__ __align__(16) float g_W[4][32][VLEN];  // [gate][unit][ x(6) | h(30) ]
__device__ float g_bias[4][32];                   // b_ih + b_hh (0 for pad units)
__device__ float g_M[HID][OUTD];                  // fused fc1+fc2
__device__ float g_bv[OUTD];                      // b2 + b1 @ W2^T

// ---------------- helpers ----------------
__device__ __forceinline__ void ffma2(ull& acc, ull a, ull b) {
    asm("fma.rn.f32x2 %0, %1, %2, %0;" : "+l"(acc) : "l"(a), "l"(b));
}
__device__ __forceinline__ ull pack2(float x, float y) {
    ull r; asm("mov.b64 %0, {%1, %2};" : "=l"(r) : "f"(x), "f"(y)); return r;
}
__device__ __forceinline__ float hsum2(ull v) {
    float2 r; asm("mov.b64 {%0, %1}, %2;" : "=f"(r.x), "=f"(r.y) : "l"(v));
    return r.x + r.y;
}
__device__ __forceinline__ float tanh_fast(float x) {
    float r; asm("tanh.approx.f32 %0, %1;" : "=f"(r) : "f"(x)); return r;
}

// ---------------- prep kernel ----------------
__global__ void prep_kernel(const float* __restrict__ Wih, const float* __restrict__ Whh,
                            const float* __restrict__ bih, const float* __restrict__ bhh,
                            const float* __restrict__ W1,  const float* __restrict__ b1,
                            const float* __restrict__ W2,  const float* __restrict__ b2) {
    int tid = threadIdx.x;
    for (int idx = tid; idx < 4 * 32 * VLEN; idx += blockDim.x) {
        int g = idx / (32 * VLEN);
        int r = idx % (32 * VLEN);
        int u = r / VLEN, j = r % VLEN;
        float w = 0.0f;
        if (u < HID) {
            if (j < INP) w = Wih[(g * HID + u) * INP + j];
            else         w = Whh[(g * HID + u) * HID + (j - INP)];
        }
        g_W[g][u][j] = w;
    }
    for (int idx = tid; idx < 4 * 32; idx += blockDim.x) {
        int g = idx / 32, u = idx % 32;
        g_bias[g][u] = (u < HID) ? (bih[g * HID + u] + bhh[g * HID + u]) : 0.0f;
    }
    for (int idx = tid; idx < HID * OUTD; idx += blockDim.x) {
        int j = idx / OUTD, o = idx % OUTD;
        float s = 0.0f;
        for (int k = 0; k < HID; k++) s += W1[k * HID + j] * W2[o * HID + k];
        g_M[j][o] = s;
    }
    for (int o = tid; o < OUTD; o += blockDim.x) {
        float s = b2[o];
        for (int k = 0; k < HID; k++) s += b1[k] * W2[o * HID + k];
        g_bv[o] = s;
    }
}

// ---------------- main persistent LSTM kernel (warp-pair domains) ----------------
__global__ void __launch_bounds__(NTHR, 1)
lstm_kernel(const float* __restrict__ X, float* __restrict__ out) {
    // per-pair state: h double-buffered [2][pair][batch][32 units], x double-buffered
    __shared__ __align__(16) float hb[2][NPAIR][BPP][32];   // 8192 B
    __shared__ __align__(16) float xb[NPAIR][2][BPP * INP]; // 1536 B

    const int tid    = threadIdx.x;
    const int lane   = tid & 31;
    const int wid    = tid >> 5;                // 0..15
    const int pr     = wid >> 1;                // pair 0..7
    const int uhalf  = wid & 1;                 // 0: units 0-15, 1: units 16-31
    const int u16    = lane & 15;               // unit within half
    const int gh     = lane >> 4;               // gate-pair: 0 -> (i,f), 1 -> (g,o)
    const int u      = uhalf * 16 + u16;        // global unit 0..31 (30 real)
    const int bfirst = (blockIdx.x * NPAIR + pr) * BPP;  // first global batch of pair
    const bool xlane = (uhalf == 0) && (lane < BPP * INP / 4);  // even warp lanes 0..5
    const int barid  = 1 + pr;

    // ---- weights for rows (gate 2gh, 2gh+1) of unit u: 2 x 18 ull ----
    ull w0[18], w1[18];
    {
        const ull* p0 = (const ull*)&g_W[2 * gh][u][0];
        const ull* p1 = (const ull*)&g_W[2 * gh + 1][u][0];
#pragma unroll
        for (int k = 0; k < 18; k++) { w0[k] = p0[k]; w1[k] = p1[k]; }
    }
    const ull bias_lo = pack2(g_bias[2 * gh][u], 0.0f);
    const ull bias_hi = pack2(g_bias[2 * gh + 1][u], 0.0f);
    // act for "lo" row: gate 0 (i, sigmoid) when gh=0; gate 2 (g~, tanh) when gh=1
    const float S = gh ? 1.0f : 0.5f;
    const float D = gh ? 0.0f : 0.5f;

    // ---- init: zero h buf 0, stage x(0) ----
    for (int i = tid; i < NPAIR * BPP * 32; i += NTHR) (&hb[0][0][0][0])[i] = 0.0f;
    if (xlane) {
        const float4 v = *(const float4*)(X + (size_t)bfirst * INP + lane * 4);
        *(float4*)&xb[pr][0][lane * 4] = v;
    }
    __syncthreads();

    // cell state for my 2 batches (b = 2*gh, 2*gh+1) of unit u
    float c0 = 0.0f, c1 = 0.0f;

    int cur = 0;
#pragma unroll 1
    for (int t = 0; t < SEQ; ++t) {
        // prefetch x(t+1) (clamped at end; value unused then)
        float4 xp;
        const int tn = (t + 1 < SEQ) ? t + 1 : t;
        if (xlane)
            xp = *(const float4*)(X + ((size_t)tn * BATCH + bfirst) * INP + lane * 4);

        const float* xr = &xb[pr][t & 1][0];

        ull alo[BPP], ahi[BPP];
#pragma unroll
        for (int b = 0; b < BPP; b++) {
            ull a0 = bias_lo, a1 = bias_hi;
            // x part: 3 ull, warp-broadcast
            ull vx0 = *(const ull*)(xr + 6 * b);
            ull vx1 = *(const ull*)(xr + 6 * b + 2);
            ull vx2 = *(const ull*)(xr + 6 * b + 4);
            ffma2(a0, w0[0], vx0); ffma2(a1, w1[0], vx0);
            ffma2(a0, w0[1], vx1); ffma2(a1, w1[1], vx1);
            ffma2(a0, w0[2], vx2); ffma2(a1, w1[2], vx2);
            // h part: 30 floats = 7 ulonglong2 + 1 ull, warp-broadcast
            const float* hrow = &hb[cur][pr][b][0];
            const ulonglong2* h2 = (const ulonglong2*)hrow;
#pragma unroll
            for (int k = 0; k < 7; k++) {
                ulonglong2 vh = h2[k];
                ffma2(a0, w0[3 + 2 * k], vh.x); ffma2(a1, w1[3 + 2 * k], vh.x);
                ffma2(a0, w0[4 + 2 * k], vh.y); ffma2(a1, w1[4 + 2 * k], vh.y);
            }
            ull vhl = *(const ull*)(hrow + 28);
            ffma2(a0, w0[17], vhl); ffma2(a1, w1[17], vhl);
            alo[b] = a0; ahi[b] = a1;
        }

        // activations + gate exchange + state update
        float* hn = &hb[cur ^ 1][pr][0][0];
#pragma unroll
        for (int b = 0; b < BPP; b += 2) {
            // my two raw gates per batch; act_lo: sigmoid(i) [gh=0] / tanh(g) [gh=1]
            float l0 = fmaf(S, tanh_fast(S * hsum2(alo[b])),     D);
            float h0 = fmaf(0.5f, tanh_fast(0.5f * hsum2(ahi[b])), 0.5f);
            float l1 = fmaf(S, tanh_fast(S * hsum2(alo[b + 1])),     D);
            float h1 = fmaf(0.5f, tanh_fast(0.5f * hsum2(ahi[b + 1])), 0.5f);
            // exchange with gate-partner lane (xor 16)
            float rl0 = __shfl_xor_sync(0xffffffffu, l0, 16);
            float rh0 = __shfl_xor_sync(0xffffffffu, h0, 16);
            float rl1 = __shfl_xor_sync(0xffffffffu, l1, 16);
            float rh1 = __shfl_xor_sync(0xffffffffu, h1, 16);
            // I update batches (2*gh, 2*gh+1): pick my/received per role
            // gh=0: si=l, sf=h, tg=rl, so=rh  (update b pair 0,1)
            // gh=1: si=rl, sf=rh, tg=l, so=h  (update b pair 2,3)
            float si0 = gh ? rl0 : l0,  sf0 = gh ? rh0 : h0;
            float tg0 = gh ? l0  : rl0, so0 = gh ? h0  : rh0;
            float si1 = gh ? rl1 : l1,  sf1 = gh ? rh1 : h1;
            float tg1 = gh ? l1  : rl1, so1 = gh ? h1  : rh1;
            // which batch pair these belong to: this iteration computed batches (b, b+1);
            // lane with gh==b/2 owns them
            if ((b >> 1) == gh) {
                c0 = fmaf(sf0, c0, si0 * tg0);
                c1 = fmaf(sf1, c1, si1 * tg1);
                hn[b * 32 + u]       = so0 * tanh_fast(c0);
                hn[(b + 1) * 32 + u] = so1 * tanh_fast(c1);
            }
        }

        // publish x(t+1)
        if (xlane) *(float4*)&xb[pr][(t + 1) & 1][lane * 4] = xp;
        // pair barrier: 64 threads (both warps of the pair)
        asm volatile("bar.sync %0, 64;" :: "r"(barid) : "memory");
        cur ^= 1;
    }

    // ---- fused fc1+fc2 epilogue over the block's 32 batches ----
    __syncthreads();
    for (int idx = tid; idx < BBLK * OUTD; idx += NTHR) {
        int lb = idx / OUTD, o = idx % OUTD;
        int p = lb / BPP, b = lb % BPP;
        float s = g_bv[o];
#pragma unroll
        for (int j = 0; j < HID; j++) s += hb[cur][p][b][j] * g_M[j][o];
        out[(size_t)(blockIdx.x * BBLK + lb) * OUTD + o] = s;
    }
}

// ---------------- launch ----------------
extern "C" void kernel_launch(void* const* d_in, const int* in_sizes, int n_in,
                              void* d_out, int out_size) {
    const float* X   = (const float*)d_in[0];
    const float* Wih = (const float*)d_in[1];
    const float* Whh = (const float*)d_in[2];
    const float* bih = (const float*)d_in[3];
    const float* bhh = (const float*)d_in[4];
    const float* W1  = (const float*)d_in[5];
    const float* b1  = (const float*)d_in[6];
    const float* W2  = (const float*)d_in[7];
    const float* b2  = (const float*)d_in[8];

    prep_kernel<<<1, 256>>>(Wih, Whh, bih, bhh, W1, b1, W2, b2);
    lstm_kernel<<<NBLK, NTHR>>>(X, (float*)d_out);
}

// round 8
// speedup vs baseline: 1.1629x; 1.1629x over previous
#include <cuda_runtime.h>

#define SEQ   600
#define BATCH 4096
#define INP   6
#define HID   30
#define OUTD  61
#define VLEN  36              // x(6) + h(30), no pad
#define NTHR  256             // 8 warps
#define WPB   8               // warps per block
#define BPW   4               // batches per warp
#define BBLK  (WPB * BPW)     // 32 batches per block
#define NBLK  (BATCH / BBLK)  // 128 blocks

typedef unsigned long long ull;

// ---------------- preprocessed weights (device globals) ----------------
__device__ __align__(16) float g_W[4][32][VLEN];  // [gate][unit][ x(6) | h(30) ]
__device__ float g_bias[4][32];                   // b_ih + b_hh (0 for pad units)
__device__ float g_M[HID][OUTD];                  // fused fc1+fc2
__device__ float g_bv[OUTD];                      // b2 + b1 @ W2^T

// ---------------- helpers ----------------
__device__ __forceinline__ void ffma2(ull& acc, ull a, ull b) {
    asm("fma.rn.f32x2 %0, %1, %2, %0;" : "+l"(acc) : "l"(a), "l"(b));
}
__device__ __forceinline__ ull pack2(float x, float y) {
    ull r; asm("mov.b64 %0, {%1, %2};" : "=l"(r) : "f"(x), "f"(y)); return r;
}
__device__ __forceinline__ float hsum2(ull v) {
    float2 r; asm("mov.b64 {%0, %1}, %2;" : "=f"(r.x), "=f"(r.y) : "l"(v));
    return r.x + r.y;
}
__device__ __forceinline__ float tanh_fast(float x) {
    float r; asm("tanh.approx.f32 %0, %1;" : "=f"(r) : "f"(x)); return r;
}
__device__ __forceinline__ float sigmoid_fast(float x) {
    return fmaf(0.5f, tanh_fast(0.5f * x), 0.5f);
}

// ---------------- prep kernel ----------------
__global__ void prep_kernel(const float* __restrict__ Wih, const float* __restrict__ Whh,
                            const float* __restrict__ bih, const float* __restrict__ bhh,
                            const float* __restrict__ W1,  const float* __restrict__ b1,
                            const float* __restrict__ W2,  const float* __restrict__ b2) {
    int tid = threadIdx.x;
    for (int idx = tid; idx < 4 * 32 * VLEN; idx += blockDim.x) {
        int g = idx / (32 * VLEN);
        int r = idx % (32 * VLEN);
        int u = r / VLEN, j = r % VLEN;
        float w = 0.0f;
        if (u < HID) {
            if (j < INP) w = Wih[(g * HID + u) * INP + j];
            else         w = Whh[(g * HID + u) * HID + (j - INP)];
        }
        g_W[g][u][j] = w;
    }
    for (int idx = tid; idx < 4 * 32; idx += blockDim.x) {
        int g = idx / 32, u = idx % 32;
        g_bias[g][u] = (u < HID) ? (bih[g * HID + u] + bhh[g * HID + u]) : 0.0f;
    }
    for (int idx = tid; idx < HID * OUTD; idx += blockDim.x) {
        int j = idx / OUTD, o = idx % OUTD;
        float s = 0.0f;
        for (int k = 0; k < HID; k++) s += W1[k * HID + j] * W2[o * HID + k];
        g_M[j][o] = s;
    }
    for (int o = tid; o < OUTD; o += blockDim.x) {
        float s = b2[o];
        for (int k = 0; k < HID; k++) s += b1[k] * W2[o * HID + k];
        g_bv[o] = s;
    }
}

// ---------------- main persistent LSTM kernel (warp-autonomous, phase-split) ----------------
__global__ void __launch_bounds__(NTHR, 1)
lstm_kernel(const float* __restrict__ X, float* __restrict__ out) {
    // per-warp state: h double-buffered, x double-buffered
    __shared__ __align__(16) float hb[2][WPB][BPW][32];   // 8192 B
    __shared__ __align__(16) float xb[WPB][2][BPW * INP]; // 1536 B

    const int tid    = threadIdx.x;
    const int lane   = tid & 31;                 // unit 0..31 (30 real, 2 pad)
    const int wid    = tid >> 5;                 // warp 0..7
    const int bfirst = (blockIdx.x * WPB + wid) * BPW;
    const bool xlane = (lane < BPW * INP / 4);   // lanes 0..5 stage x

    // ---- weights for (all 4 gates, unit=lane): 4 x 18 ull = 144 regs ----
    ull w[4][18];
    ull bias2[4];
#pragma unroll
    for (int g = 0; g < 4; g++) {
        const ull* wp = (const ull*)&g_W[g][lane][0];
#pragma unroll
        for (int k = 0; k < 18; k++) w[g][k] = wp[k];
        bias2[g] = pack2(g_bias[g][lane], 0.0f);
    }

    // ---- init: zero h buf 0, stage x(0) ----
#pragma unroll
    for (int b = 0; b < BPW; b++) hb[0][wid][b][lane] = 0.0f;
    if (xlane) {
        const float4 v = *(const float4*)(X + (size_t)bfirst * INP + lane * 4);
        *(float4*)&xb[wid][0][lane * 4] = v;
    }
    __syncwarp();

    float c[BPW] = {0.0f, 0.0f, 0.0f, 0.0f};

    int cur = 0;
#pragma unroll 1
    for (int t = 0; t < SEQ; ++t) {
        // prefetch x(t+1) into registers (clamped at end; value unused then)
        float4 xp;
        const int tn = (t + 1 < SEQ) ? t + 1 : t;
        if (xlane)
            xp = *(const float4*)(X + ((size_t)tn * BATCH + bfirst) * INP + lane * 4);

        const float* xr = &xb[wid][t & 1][0];

        // ===== Phase 1: all MACs, all batches (LDS only; no STS yet) =====
        ull acc[BPW][4];
#pragma unroll
        for (int b = 0; b < BPW; b++) {
            ull a0 = bias2[0], a1 = bias2[1], a2 = bias2[2], a3 = bias2[3];
            // x part: 3 ull, warp-broadcast
            ull vx0 = *(const ull*)(xr + 6 * b);
            ull vx1 = *(const ull*)(xr + 6 * b + 2);
            ull vx2 = *(const ull*)(xr + 6 * b + 4);
            ffma2(a0, w[0][0], vx0); ffma2(a1, w[1][0], vx0);
            ffma2(a2, w[2][0], vx0); ffma2(a3, w[3][0], vx0);
            ffma2(a0, w[0][1], vx1); ffma2(a1, w[1][1], vx1);
            ffma2(a2, w[2][1], vx1); ffma2(a3, w[3][1], vx1);
            ffma2(a0, w[0][2], vx2); ffma2(a1, w[1][2], vx2);
            ffma2(a2, w[2][2], vx2); ffma2(a3, w[3][2], vx2);
            // h part: 30 floats = 7 x LDS.128 + 1 x LDS.64, warp-broadcast
            const float* hrow = &hb[cur][wid][b][0];
            const ulonglong2* h2 = (const ulonglong2*)hrow;
#pragma unroll
            for (int k = 0; k < 7; k++) {
                ulonglong2 vh = h2[k];
                ffma2(a0, w[0][3 + 2 * k], vh.x); ffma2(a1, w[1][3 + 2 * k], vh.x);
                ffma2(a2, w[2][3 + 2 * k], vh.x); ffma2(a3, w[3][3 + 2 * k], vh.x);
                ffma2(a0, w[0][4 + 2 * k], vh.y); ffma2(a1, w[1][4 + 2 * k], vh.y);
                ffma2(a2, w[2][4 + 2 * k], vh.y); ffma2(a3, w[3][4 + 2 * k], vh.y);
            }
            ull vhl = *(const ull*)(hrow + 28);
            ffma2(a0, w[0][17], vhl); ffma2(a1, w[1][17], vhl);
            ffma2(a2, w[2][17], vhl); ffma2(a3, w[3][17], vhl);
            acc[b][0] = a0; acc[b][1] = a1; acc[b][2] = a2; acc[b][3] = a3;
        }

        // ===== Phase 2: all activations + state updates (ILP-4 chains), then stores =====
        float hv[BPW];
#pragma unroll
        for (int b = 0; b < BPW; b++) {
            float si = sigmoid_fast(hsum2(acc[b][0]));
            float sf = sigmoid_fast(hsum2(acc[b][1]));
            float tg = tanh_fast   (hsum2(acc[b][2]));
            float so = sigmoid_fast(hsum2(acc[b][3]));
            c[b] = fmaf(sf, c[b], si * tg);
            hv[b] = so * tanh_fast(c[b]);
        }
#pragma unroll
        for (int b = 0; b < BPW; b++)
            hb[cur ^ 1][wid][b][lane] = hv[b];   // pad lanes write 0 naturally

        // publish x(t+1) into the other x buffer
        if (xlane) *(float4*)&xb[wid][(t + 1) & 1][lane * 4] = xp;
        __syncwarp();   // cross-lane visibility of h(t) and x(t+1)
        cur ^= 1;
    }

    // ---- fused fc1+fc2 epilogue over the block's 32 batches ----
    __syncthreads();
    for (int idx = tid; idx < BBLK * OUTD; idx += NTHR) {
        int lb = idx / OUTD, o = idx % OUTD;
        int ww = lb / BPW, b = lb % BPW;
        float s = g_bv[o];
#pragma unroll
        for (int j = 0; j < HID; j++) s += hb[cur][ww][b][j] * g_M[j][o];
        out[(size_t)(blockIdx.x * BBLK + lb) * OUTD + o] = s;
    }
}

// ---------------- launch ----------------
extern "C" void kernel_launch(void* const* d_in, const int* in_sizes, int n_in,
                              void* d_out, int out_size) {
    const float* X   = (const float*)d_in[0];
    const float* Wih = (const float*)d_in[1];
    const float* Whh = (const float*)d_in[2];
    const float* bih = (const float*)d_in[3];
    const float* bhh = (const float*)d_in[4];
    const float* W1  = (const float*)d_in[5];
    const float* b1  = (const float*)d_in[6];
    const float* W2  = (const float*)d_in[7];
    const float* b2  = (const float*)d_in[8];

    prep_kernel<<<1, 256>>>(Wih, Whh, bih, bhh, W1, b1, W2, b2);
    lstm_kernel<<<NBLK, NTHR>>>(X, (float*)d_out);
}